// round 6
// baseline (speedup 1.0000x reference)
#include <cuda_runtime.h>
#include <cuda_bf16.h>
#include <cuda_fp16.h>
#include <cstdint>

// Sizes
#define W_WORDS 4096
#define LCH 32
#define D2 512
#define D4 1024
#define KDIM 1536   // 3*512

// GEMM tiling
#define GM 128
#define GN 64
#define GK 32
#define NK (KDIM / GK)            // 48
#define A_TILE (GM * GK * 2)      // 8192 B (fp16)
#define B_TILE (GN * GK * 2)      // 4096 B
#define STAGE_B (A_TILE + 2 * B_TILE)       // 16384
#define NSTAGE 3
#define SMEM_DYN (NSTAGE * STAGE_B)         // 49152

#define LO_SCALE 2048.0f
#define LO_INV   (1.0f / 2048.0f)

// ---------------- scratch ----------------
__device__ __align__(128) float  g_Wt[3 * 256 * 256];
__device__ __align__(128) float  g_T[3 * 128 * 256];
__device__ __align__(128) __half g_ua[(W_WORDS + 2) * D2];   // u in fp16 (unsplit)
__device__ __align__(128) __half g_Bh[D2 * KDIM];            // B hi  [o][p] K-major
__device__ __align__(128) __half g_Bl[D2 * KDIM];            // B lo * 2048
__device__ __align__(128) unsigned g_rkeys[D2];
__device__ __align__(128) float  g_h[D4];

// ---------------- helpers ----------------
__device__ __forceinline__ uint32_t smem_u32(const void* p) {
    uint32_t a;
    asm("{ .reg .u64 t; cvta.to.shared.u64 t, %1; cvt.u32.u64 %0, t; }" : "=r"(a) : "l"(p));
    return a;
}
__device__ __forceinline__ void ldmx4(uint32_t* r, uint32_t addr) {
    asm volatile("ldmatrix.sync.aligned.m8n8.x4.shared.b16 {%0,%1,%2,%3}, [%4];"
                 : "=r"(r[0]), "=r"(r[1]), "=r"(r[2]), "=r"(r[3]) : "r"(addr));
}
__device__ __forceinline__ void mma_f16(float* c, const uint32_t* a, uint32_t b0, uint32_t b1) {
    asm volatile("mma.sync.aligned.m16n8k16.row.col.f32.f16.f16.f32 "
                 "{%0,%1,%2,%3}, {%4,%5,%6,%7}, {%8,%9}, {%0,%1,%2,%3};"
                 : "+f"(c[0]), "+f"(c[1]), "+f"(c[2]), "+f"(c[3])
                 : "r"(a[0]), "r"(a[1]), "r"(a[2]), "r"(a[3]), "r"(b0), "r"(b1));
}
__device__ __forceinline__ void cp16(uint32_t dst, const void* src) {
    asm volatile("cp.async.cg.shared.global [%0], [%1], 16;" :: "r"(dst), "l"(src));
}
#define CP_COMMIT() asm volatile("cp.async.commit_group;" ::: "memory")
#define CP_WAIT1()  asm volatile("cp.async.wait_group 1;" ::: "memory")

// ---------------- prep kernels ----------------
__global__ void k_tr_wc(const float* __restrict__ wc) {
    int b = blockIdx.x;            // 768 = 3*256
    int k = b / 256, i = b % 256;
    int d = threadIdx.x;
    g_Wt[k * 65536 + i * 256 + d] = wc[d * 768 + i * 3 + k];
}

__global__ void k_prep_B(const float* __restrict__ ws) {
    int o = blockIdx.x;            // 512
    for (int p = threadIdx.x; p < KDIM; p += 256) {
        int kk = p >> 9, i = p & 511;
        float v = ws[o * KDIM + i * 3 + kk];
        __half h = __float2half(v);
        g_Bh[o * KDIM + p] = h;
        g_Bl[o * KDIM + p] = __float2half((v - __half2float(h)) * LO_SCALE);
    }
    if (blockIdx.x == 0) { g_rkeys[threadIdx.x] = 0u; g_rkeys[threadIdx.x + 256] = 0u; }
}

__global__ void k_tables(const float* __restrict__ chr_emb) {
    __shared__ float ce[2][256];
    int d = threadIdx.x;
    int c0 = blockIdx.x * 2;
    ce[0][d] = chr_emb[c0 * 256 + d];
    ce[1][d] = chr_emb[(c0 + 1) * 256 + d];
    __syncthreads();
    float a00 = 0.f, a01 = 0.f, a02 = 0.f, a10 = 0.f, a11 = 0.f, a12 = 0.f;
    #pragma unroll 8
    for (int i = 0; i < 256; i++) {
        float e0 = ce[0][i], e1 = ce[1][i];
        float w0 = g_Wt[i * 256 + d];
        float w1 = g_Wt[65536 + i * 256 + d];
        float w2 = g_Wt[131072 + i * 256 + d];
        a00 += e0 * w0; a01 += e0 * w1; a02 += e0 * w2;
        a10 += e1 * w0; a11 += e1 * w1; a12 += e1 * w2;
    }
    g_T[c0 * 256 + d] = a00;
    g_T[32768 + c0 * 256 + d] = a01;
    g_T[65536 + c0 * 256 + d] = a02;
    g_T[(c0 + 1) * 256 + d] = a10;
    g_T[32768 + (c0 + 1) * 256 + d] = a11;
    g_T[65536 + (c0 + 1) * 256 + d] = a12;
}

// ---------------- build u (fp16, padded) ----------------
__global__ void k_build_u(const int* __restrict__ words,
                          const int* __restrict__ wic,
                          const float* __restrict__ word_emb,
                          const float* __restrict__ cb) {
    int w = blockIdx.x;            // 4096
    int t = threadIdx.x;           // 128
    __shared__ int codes[LCH];
    if (t < LCH) codes[t] = wic[w * LCH + t];
    __syncthreads();

    const float2* WE = (const float2*)word_emb;
    float2 wv = WE[(size_t)words[w] * 128 + t];
    __half2* UA = (__half2*)g_ua;  // row = 256 half2
    UA[(w + 1) * 256 + t] = __floats2half2_rn(wv.x, wv.y);

    const float2* T0 = (const float2*)g_T;
    const float2* T1 = (const float2*)(g_T + 32768);
    const float2* T2 = (const float2*)(g_T + 65536);
    float2 bb = ((const float2*)cb)[t];

    int c = codes[0];
    float2 a0 = T0[c * 128 + t], a1 = T1[c * 128 + t], a2 = T2[c * 128 + t];
    float2 accA = make_float2(bb.x + a1.x, bb.y + a1.y);
    float2 accB = make_float2(bb.x + a0.x, bb.y + a0.y);
    float2 m = make_float2(-1e30f, -1e30f);
    (void)a2;
    #pragma unroll
    for (int s = 1; s < LCH; s++) {
        c = codes[s];
        a0 = T0[c * 128 + t]; a1 = T1[c * 128 + t]; a2 = T2[c * 128 + t];
        m.x = fmaxf(m.x, accA.x + a2.x);
        m.y = fmaxf(m.y, accA.y + a2.y);
        accA.x = accB.x + a1.x; accA.y = accB.y + a1.y;
        accB.x = bb.x + a0.x;   accB.y = bb.y + a0.y;
    }
    m.x = fmaxf(m.x, accA.x);
    m.y = fmaxf(m.y, accA.y);
    UA[(w + 1) * 256 + 128 + t] = __floats2half2_rn(m.x, m.y);

    __half2 z = __floats2half2_rn(0.f, 0.f);
    if (w == 0) { UA[t] = z; UA[128 + t] = z; }
    if (w == W_WORDS - 1) {
        size_t r = (size_t)(W_WORDS + 1) * 256;
        UA[r + t] = z; UA[r + 128 + t] = z;
    }
}

// ---------------- GEMM: fp16 2-product (A * (Bh + Bl/2048)) + fused column max ----------------
__global__ __launch_bounds__(256, 2) void k_gemm_mma() {
    extern __shared__ __align__(128) char smem[];
    uint32_t sb = smem_u32(smem);
    int tid = threadIdx.x;
    int lane = tid & 31, wq = tid >> 5;
    int wm = wq & 3, wn = wq >> 2;       // 4 m-warps x 2 n-warps; warp tile 32x32
    int n0 = blockIdx.x * GN;
    int w0 = blockIdx.y * GM;

    float acc1[2][4][4], acc2[2][4][4];  // hi product / lo product
    #pragma unroll
    for (int a = 0; a < 2; a++)
        #pragma unroll
        for (int f = 0; f < 4; f++)
            #pragma unroll
            for (int r = 0; r < 4; r++) { acc1[a][f][r] = 0.f; acc2[a][f][r] = 0.f; }

    auto issue_stage = [&](int ck, int s) {
        int p0 = ck * GK;
        int kk = p0 >> 9, i0 = p0 & 511;
        uint32_t st = sb + s * STAGE_B;
        #pragma unroll
        for (int q = 0; q < 4; q++) {
            int idx = tid + q * 256;      // 0..1023
            if (idx < 512) {              // A tile: 512 x 16B
                int r = idx >> 2, c4 = idx & 3;
                uint32_t dst = st + r * 64 + ((c4 ^ ((r >> 1) & 3)) << 4);
                const __half* src = g_ua + (size_t)(w0 + kk + r) * D2 + i0 + c4 * 8;
                cp16(dst, src);
            } else {                      // B: Bh then Bl, 256 x 16B each
                int j = idx - 512;
                int sub = j >> 8;
                int jj = j & 255;
                int r = jj >> 2, c4 = jj & 3;
                uint32_t dst = st + A_TILE + sub * B_TILE + r * 64 + ((c4 ^ ((r >> 1) & 3)) << 4);
                const __half* src = (sub ? g_Bl : g_Bh) + (size_t)(n0 + r) * KDIM + p0 + c4 * 8;
                cp16(dst, src);
            }
        }
        CP_COMMIT();
    };

    issue_stage(0, 0);
    issue_stage(1, 1);

    for (int ck = 0; ck < NK; ck++) {
        CP_WAIT1();
        __syncthreads();
        if (ck + 2 < NK) issue_stage(ck + 2, (ck + 2) % NSTAGE);
        else CP_COMMIT();

        uint32_t st = sb + (ck % NSTAGE) * STAGE_B;
        uint32_t aA = st, bH = st + A_TILE, bL = st + A_TILE + B_TILE;
        #pragma unroll
        for (int ks = 0; ks < 2; ks++) {
            uint32_t ah[2][4];
            #pragma unroll
            for (int mf = 0; mf < 2; mf++) {
                int row = wm * 32 + mf * 16 + (lane & 7) + ((lane >> 3) & 1) * 8;
                int c = 2 * ks + (lane >> 4);
                uint32_t off = (uint32_t)(row * 64) + (uint32_t)((c ^ ((row >> 1) & 3)) << 4);
                ldmx4(ah[mf], aA + off);
            }
            #pragma unroll
            for (int bq = 0; bq < 2; bq++) {
                int row = wn * 32 + bq * 16 + (lane & 7) + ((lane >> 3) & 1) * 8;
                int c = 2 * ks + (lane >> 4);
                uint32_t off = (uint32_t)(row * 64) + (uint32_t)((c ^ ((row >> 1) & 3)) << 4);
                uint32_t bh[4], bl[4];
                ldmx4(bh, bH + off);
                ldmx4(bl, bL + off);
                #pragma unroll
                for (int mf = 0; mf < 2; mf++) {
                    mma_f16(acc1[mf][2 * bq],     ah[mf], bh[0], bh[2]);
                    mma_f16(acc1[mf][2 * bq + 1], ah[mf], bh[1], bh[3]);
                    mma_f16(acc2[mf][2 * bq],     ah[mf], bl[0], bl[2]);
                    mma_f16(acc2[mf][2 * bq + 1], ah[mf], bl[1], bl[3]);
                }
            }
        }
    }

    // epilogue: merge (acc1 + acc2/2048), column max over tile's 128 rows
    __syncthreads();
    float* red = (float*)smem;   // [4 wm][64 cols]
    #pragma unroll
    for (int f = 0; f < 4; f++) {
        float t0 = -1e30f, t1 = -1e30f;
        #pragma unroll
        for (int mf = 0; mf < 2; mf++) {
            float v0 = fmaf(acc2[mf][f][0], LO_INV, acc1[mf][f][0]);
            float v1 = fmaf(acc2[mf][f][1], LO_INV, acc1[mf][f][1]);
            float v2 = fmaf(acc2[mf][f][2], LO_INV, acc1[mf][f][2]);
            float v3 = fmaf(acc2[mf][f][3], LO_INV, acc1[mf][f][3]);
            t0 = fmaxf(t0, fmaxf(v0, v2));
            t1 = fmaxf(t1, fmaxf(v1, v3));
        }
        #pragma unroll
        for (int off = 4; off < 32; off <<= 1) {
            t0 = fmaxf(t0, __shfl_xor_sync(0xffffffffu, t0, off));
            t1 = fmaxf(t1, __shfl_xor_sync(0xffffffffu, t1, off));
        }
        if (lane < 4) {
            red[wm * 64 + wn * 32 + f * 8 + 2 * lane]     = t0;
            red[wm * 64 + wn * 32 + f * 8 + 2 * lane + 1] = t1;
        }
    }
    __syncthreads();
    if (tid < 64) {
        float m = red[tid];
        #pragma unroll
        for (int q = 1; q < 4; q++) m = fmaxf(m, red[q * 64 + tid]);
        unsigned u = __float_as_uint(m);
        unsigned key = (u & 0x80000000u) ? ~u : (u | 0x80000000u);
        atomicMax(&g_rkeys[n0 + tid], key);
    }
}

// ---------------- head ----------------
__global__ void k_h(const float* __restrict__ sb,
                    const float* __restrict__ w1,
                    const float* __restrict__ b1) {
    __shared__ float rs[D2];
    int tid = threadIdx.x;
    for (int j = tid; j < D2; j += 256) {
        unsigned key = g_rkeys[j];
        unsigned u = (key & 0x80000000u) ? (key & 0x7FFFFFFFu) : ~key;
        rs[j] = __uint_as_float(u) + sb[j];
    }
    __syncthreads();
    int g = tid >> 4, s = tid & 15;
    int o = blockIdx.x * 16 + g;
    float accv = 0.f;
    for (int j = s; j < D2; j += 16) accv += w1[o * D2 + j] * rs[j];
    #pragma unroll
    for (int off = 8; off; off >>= 1) accv += __shfl_down_sync(0xffffffffu, accv, off, 16);
    if (s == 0) g_h[o] = tanhf(accv + b1[o]);
}

__global__ void k_out(const float* __restrict__ w2,
                      const float* __restrict__ b2,
                      float* __restrict__ out) {
    int j = threadIdx.x >> 5, lane = threadIdx.x & 31;
    float accv = 0.f;
    for (int l = lane; l < D4; l += 32) accv += g_h[l] * w2[j * D4 + l];
    #pragma unroll
    for (int off = 16; off; off >>= 1) accv += __shfl_down_sync(0xffffffffu, accv, off);
    if (lane == 0) out[j] = accv + b2[j];
}

extern "C" void kernel_launch(void* const* d_in, const int* in_sizes, int n_in,
                              void* d_out, int out_size) {
    const int*   words       = (const int*)d_in[0];
    const int*   wic         = (const int*)d_in[1];
    const float* word_emb    = (const float*)d_in[2];
    const float* chr_emb     = (const float*)d_in[3];
    const float* conv_chr_w  = (const float*)d_in[4];
    const float* conv_chr_b  = (const float*)d_in[5];
    const float* conv_sent_w = (const float*)d_in[6];
    const float* conv_sent_b = (const float*)d_in[7];
    const float* w1          = (const float*)d_in[8];
    const float* b1          = (const float*)d_in[9];
    const float* w2          = (const float*)d_in[10];
    const float* b2          = (const float*)d_in[11];
    float* out = (float*)d_out;

    cudaFuncSetAttribute(k_gemm_mma, cudaFuncAttributeMaxDynamicSharedMemorySize, SMEM_DYN);

    k_tr_wc<<<768, 256>>>(conv_chr_w);
    k_prep_B<<<512, 256>>>(conv_sent_w);
    k_tables<<<64, 256>>>(chr_emb);
    k_build_u<<<W_WORDS, 128>>>(words, wic, word_emb, conv_chr_b);
    dim3 g3(D2 / GN, W_WORDS / GM);     // 8 x 32 = 256 CTAs
    k_gemm_mma<<<g3, 256, SMEM_DYN>>>();
    k_h<<<64, 256>>>(conv_sent_b, w1, b1);
    k_out<<<1, 64>>>(w2, b2, out);
}

// round 7
// speedup vs baseline: 1.4740x; 1.4740x over previous
#include <cuda_runtime.h>
#include <cuda_bf16.h>
#include <cuda_fp16.h>
#include <cstdint>

// Sizes
#define W_WORDS 4096
#define LCH 32
#define D2 512
#define D4 1024
#define KDIM 1536   // 3*512

// GEMM tiling
#define GM 128
#define GN 64
#define GK 32
#define NK (KDIM / GK)            // 48
#define A_TILE (GM * GK * 2)      // 8192 B (fp16)
#define B_TILE (GN * GK * 2)      // 4096 B
#define STAGE_B (A_TILE + 2 * B_TILE)       // 16384
#define NSTAGE 3
#define SMEM_DYN (NSTAGE * STAGE_B)         // 49152

#define LO_SCALE 2048.0f
#define LO_INV   (1.0f / 2048.0f)

// ---------------- scratch ----------------
__device__ __align__(128) float  g_Wt[3 * 256 * 256];
__device__ __align__(128) __half g_Th[3 * 128 * 256];        // fp16 lookup tables
__device__ __align__(128) __half g_ua[(W_WORDS + 2) * D2];   // u in fp16 (unsplit)
__device__ __align__(128) __half g_Bh[D2 * KDIM];            // B hi  [o][p] K-major
__device__ __align__(128) __half g_Bl[D2 * KDIM];            // B lo * 2048
__device__ __align__(128) unsigned g_rkeys[D2];
__device__ __align__(128) float  g_h[D4];

// ---------------- helpers ----------------
__device__ __forceinline__ uint32_t smem_u32(const void* p) {
    uint32_t a;
    asm("{ .reg .u64 t; cvta.to.shared.u64 t, %1; cvt.u32.u64 %0, t; }" : "=r"(a) : "l"(p));
    return a;
}
__device__ __forceinline__ void ldmx4(uint32_t* r, uint32_t addr) {
    asm volatile("ldmatrix.sync.aligned.m8n8.x4.shared.b16 {%0,%1,%2,%3}, [%4];"
                 : "=r"(r[0]), "=r"(r[1]), "=r"(r[2]), "=r"(r[3]) : "r"(addr));
}
__device__ __forceinline__ void mma_f16(float* c, const uint32_t* a, uint32_t b0, uint32_t b1) {
    asm volatile("mma.sync.aligned.m16n8k16.row.col.f32.f16.f16.f32 "
                 "{%0,%1,%2,%3}, {%4,%5,%6,%7}, {%8,%9}, {%0,%1,%2,%3};"
                 : "+f"(c[0]), "+f"(c[1]), "+f"(c[2]), "+f"(c[3])
                 : "r"(a[0]), "r"(a[1]), "r"(a[2]), "r"(a[3]), "r"(b0), "r"(b1));
}
__device__ __forceinline__ void cp16(uint32_t dst, const void* src) {
    asm volatile("cp.async.cg.shared.global [%0], [%1], 16;" :: "r"(dst), "l"(src));
}
#define CP_COMMIT() asm volatile("cp.async.commit_group;" ::: "memory")
#define CP_WAIT1()  asm volatile("cp.async.wait_group 1;" ::: "memory")

// ---------------- prep kernels ----------------
__global__ void k_tr_wc(const float* __restrict__ wc) {
    int b = blockIdx.x;            // 768 = 3*256
    int k = b / 256, i = b % 256;
    int d = threadIdx.x;
    g_Wt[k * 65536 + i * 256 + d] = wc[d * 768 + i * 3 + k];
}

__global__ void k_prep_B(const float* __restrict__ ws) {
    int o = blockIdx.x;            // 512
    for (int p = threadIdx.x; p < KDIM; p += 256) {
        int kk = p >> 9, i = p & 511;
        float v = ws[o * KDIM + i * 3 + kk];
        __half h = __float2half(v);
        g_Bh[o * KDIM + p] = h;
        g_Bl[o * KDIM + p] = __float2half((v - __half2float(h)) * LO_SCALE);
    }
    if (blockIdx.x == 0) { g_rkeys[threadIdx.x] = 0u; g_rkeys[threadIdx.x + 256] = 0u; }
}

// tables computed in fp32, stored fp16
__global__ void k_tables(const float* __restrict__ chr_emb) {
    __shared__ float ce[2][256];
    int d = threadIdx.x;
    int c0 = blockIdx.x * 2;
    ce[0][d] = chr_emb[c0 * 256 + d];
    ce[1][d] = chr_emb[(c0 + 1) * 256 + d];
    __syncthreads();
    float a00 = 0.f, a01 = 0.f, a02 = 0.f, a10 = 0.f, a11 = 0.f, a12 = 0.f;
    #pragma unroll 8
    for (int i = 0; i < 256; i++) {
        float e0 = ce[0][i], e1 = ce[1][i];
        float w0 = g_Wt[i * 256 + d];
        float w1 = g_Wt[65536 + i * 256 + d];
        float w2 = g_Wt[131072 + i * 256 + d];
        a00 += e0 * w0; a01 += e0 * w1; a02 += e0 * w2;
        a10 += e1 * w0; a11 += e1 * w1; a12 += e1 * w2;
    }
    g_Th[c0 * 256 + d]                  = __float2half(a00);
    g_Th[32768 + c0 * 256 + d]          = __float2half(a01);
    g_Th[65536 + c0 * 256 + d]          = __float2half(a02);
    g_Th[(c0 + 1) * 256 + d]            = __float2half(a10);
    g_Th[32768 + (c0 + 1) * 256 + d]    = __float2half(a11);
    g_Th[65536 + (c0 + 1) * 256 + d]    = __float2half(a12);
}

// ---------------- build u (fp16 tables, fp32 accumulation, fp16 output) ----------------
__global__ void k_build_u(const int* __restrict__ words,
                          const int* __restrict__ wic,
                          const float* __restrict__ word_emb,
                          const float* __restrict__ cb) {
    int w = blockIdx.x;            // 4096
    int t = threadIdx.x;           // 128
    __shared__ int codes[LCH];
    if (t < LCH) codes[t] = wic[w * LCH + t];
    __syncthreads();

    const float2* WE = (const float2*)word_emb;
    float2 wv = WE[(size_t)words[w] * 128 + t];
    __half2* UA = (__half2*)g_ua;  // row = 256 half2
    UA[(w + 1) * 256 + t] = __floats2half2_rn(wv.x, wv.y);

    const __half2* T0 = (const __half2*)g_Th;            // each table = 16384 half2
    const __half2* T1 = T0 + 16384;
    const __half2* T2 = T0 + 32768;
    float2 bb = ((const float2*)cb)[t];

    int c = codes[0];
    float2 a0 = __half22float2(T0[c * 128 + t]);
    float2 a1 = __half22float2(T1[c * 128 + t]);
    float2 a2 = __half22float2(T2[c * 128 + t]);
    float2 accA = make_float2(bb.x + a1.x, bb.y + a1.y);
    float2 accB = make_float2(bb.x + a0.x, bb.y + a0.y);
    float2 m = make_float2(-1e30f, -1e30f);
    (void)a2;
    #pragma unroll
    for (int s = 1; s < LCH; s++) {
        c = codes[s];
        a0 = __half22float2(T0[c * 128 + t]);
        a1 = __half22float2(T1[c * 128 + t]);
        a2 = __half22float2(T2[c * 128 + t]);
        m.x = fmaxf(m.x, accA.x + a2.x);
        m.y = fmaxf(m.y, accA.y + a2.y);
        accA.x = accB.x + a1.x; accA.y = accB.y + a1.y;
        accB.x = bb.x + a0.x;   accB.y = bb.y + a0.y;
    }
    m.x = fmaxf(m.x, accA.x);
    m.y = fmaxf(m.y, accA.y);
    UA[(w + 1) * 256 + 128 + t] = __floats2half2_rn(m.x, m.y);

    __half2 z = __floats2half2_rn(0.f, 0.f);
    if (w == 0) { UA[t] = z; UA[128 + t] = z; }
    if (w == W_WORDS - 1) {
        size_t r = (size_t)(W_WORDS + 1) * 256;
        UA[r + t] = z; UA[r + 128 + t] = z;
    }
}

// ---------------- GEMM: fp16 2-product (A * (Bh + Bl/2048)) + fused column max ----------------
__global__ __launch_bounds__(256, 2) void k_gemm_mma() {
    extern __shared__ __align__(128) char smem[];
    uint32_t sb = smem_u32(smem);
    int tid = threadIdx.x;
    int lane = tid & 31, wq = tid >> 5;
    int wm = wq & 3, wn = wq >> 2;       // 4 m-warps x 2 n-warps; warp tile 32x32
    int n0 = blockIdx.x * GN;
    int w0 = blockIdx.y * GM;

    float acc1[2][4][4], acc2[2][4][4];  // hi product / lo product
    #pragma unroll
    for (int a = 0; a < 2; a++)
        #pragma unroll
        for (int f = 0; f < 4; f++)
            #pragma unroll
            for (int r = 0; r < 4; r++) { acc1[a][f][r] = 0.f; acc2[a][f][r] = 0.f; }

    auto issue_stage = [&](int ck, int s) {
        int p0 = ck * GK;
        int kk = p0 >> 9, i0 = p0 & 511;
        uint32_t st = sb + s * STAGE_B;
        #pragma unroll
        for (int q = 0; q < 4; q++) {
            int idx = tid + q * 256;      // 0..1023
            if (idx < 512) {              // A tile: 512 x 16B
                int r = idx >> 2, c4 = idx & 3;
                uint32_t dst = st + r * 64 + ((c4 ^ ((r >> 1) & 3)) << 4);
                const __half* src = g_ua + (size_t)(w0 + kk + r) * D2 + i0 + c4 * 8;
                cp16(dst, src);
            } else {                      // B: Bh then Bl, 256 x 16B each
                int j = idx - 512;
                int sub = j >> 8;
                int jj = j & 255;
                int r = jj >> 2, c4 = jj & 3;
                uint32_t dst = st + A_TILE + sub * B_TILE + r * 64 + ((c4 ^ ((r >> 1) & 3)) << 4);
                const __half* src = (sub ? g_Bl : g_Bh) + (size_t)(n0 + r) * KDIM + p0 + c4 * 8;
                cp16(dst, src);
            }
        }
        CP_COMMIT();
    };

    issue_stage(0, 0);
    issue_stage(1, 1);

    for (int ck = 0; ck < NK; ck++) {
        CP_WAIT1();
        __syncthreads();
        if (ck + 2 < NK) issue_stage(ck + 2, (ck + 2) % NSTAGE);
        else CP_COMMIT();

        uint32_t st = sb + (ck % NSTAGE) * STAGE_B;
        uint32_t aA = st, bH = st + A_TILE, bL = st + A_TILE + B_TILE;
        #pragma unroll
        for (int ks = 0; ks < 2; ks++) {
            uint32_t ah[2][4];
            #pragma unroll
            for (int mf = 0; mf < 2; mf++) {
                int row = wm * 32 + mf * 16 + (lane & 7) + ((lane >> 3) & 1) * 8;
                int c = 2 * ks + (lane >> 4);
                uint32_t off = (uint32_t)(row * 64) + (uint32_t)((c ^ ((row >> 1) & 3)) << 4);
                ldmx4(ah[mf], aA + off);
            }
            #pragma unroll
            for (int bq = 0; bq < 2; bq++) {
                int row = wn * 32 + bq * 16 + (lane & 7) + ((lane >> 3) & 1) * 8;
                int c = 2 * ks + (lane >> 4);
                uint32_t off = (uint32_t)(row * 64) + (uint32_t)((c ^ ((row >> 1) & 3)) << 4);
                uint32_t bh[4], bl[4];
                ldmx4(bh, bH + off);
                ldmx4(bl, bL + off);
                #pragma unroll
                for (int mf = 0; mf < 2; mf++) {
                    mma_f16(acc1[mf][2 * bq],     ah[mf], bh[0], bh[2]);
                    mma_f16(acc1[mf][2 * bq + 1], ah[mf], bh[1], bh[3]);
                    mma_f16(acc2[mf][2 * bq],     ah[mf], bl[0], bl[2]);
                    mma_f16(acc2[mf][2 * bq + 1], ah[mf], bl[1], bl[3]);
                }
            }
        }
    }

    // epilogue: merge (acc1 + acc2/2048), column max over tile's 128 rows
    __syncthreads();
    float* red = (float*)smem;   // [4 wm][64 cols]
    #pragma unroll
    for (int f = 0; f < 4; f++) {
        float t0 = -1e30f, t1 = -1e30f;
        #pragma unroll
        for (int mf = 0; mf < 2; mf++) {
            float v0 = fmaf(acc2[mf][f][0], LO_INV, acc1[mf][f][0]);
            float v1 = fmaf(acc2[mf][f][1], LO_INV, acc1[mf][f][1]);
            float v2 = fmaf(acc2[mf][f][2], LO_INV, acc1[mf][f][2]);
            float v3 = fmaf(acc2[mf][f][3], LO_INV, acc1[mf][f][3]);
            t0 = fmaxf(t0, fmaxf(v0, v2));
            t1 = fmaxf(t1, fmaxf(v1, v3));
        }
        #pragma unroll
        for (int off = 4; off < 32; off <<= 1) {
            t0 = fmaxf(t0, __shfl_xor_sync(0xffffffffu, t0, off));
            t1 = fmaxf(t1, __shfl_xor_sync(0xffffffffu, t1, off));
        }
        if (lane < 4) {
            red[wm * 64 + wn * 32 + f * 8 + 2 * lane]     = t0;
            red[wm * 64 + wn * 32 + f * 8 + 2 * lane + 1] = t1;
        }
    }
    __syncthreads();
    if (tid < 64) {
        float m = red[tid];
        #pragma unroll
        for (int q = 1; q < 4; q++) m = fmaxf(m, red[q * 64 + tid]);
        unsigned u = __float_as_uint(m);
        unsigned key = (u & 0x80000000u) ? ~u : (u | 0x80000000u);
        atomicMax(&g_rkeys[n0 + tid], key);
    }
}

// ---------------- head ----------------
__global__ void k_h(const float* __restrict__ sb,
                    const float* __restrict__ w1,
                    const float* __restrict__ b1) {
    __shared__ float rs[D2];
    int tid = threadIdx.x;
    for (int j = tid; j < D2; j += 256) {
        unsigned key = g_rkeys[j];
        unsigned u = (key & 0x80000000u) ? (key & 0x7FFFFFFFu) : ~key;
        rs[j] = __uint_as_float(u) + sb[j];
    }
    __syncthreads();
    int g = tid >> 4, s = tid & 15;
    int o = blockIdx.x * 16 + g;
    float accv = 0.f;
    for (int j = s; j < D2; j += 16) accv += w1[o * D2 + j] * rs[j];
    #pragma unroll
    for (int off = 8; off; off >>= 1) accv += __shfl_down_sync(0xffffffffu, accv, off, 16);
    if (s == 0) g_h[o] = tanhf(accv + b1[o]);
}

__global__ void k_out(const float* __restrict__ w2,
                      const float* __restrict__ b2,
                      float* __restrict__ out) {
    int j = threadIdx.x >> 5, lane = threadIdx.x & 31;
    float accv = 0.f;
    for (int l = lane; l < D4; l += 32) accv += g_h[l] * w2[j * D4 + l];
    #pragma unroll
    for (int off = 16; off; off >>= 1) accv += __shfl_down_sync(0xffffffffu, accv, off);
    if (lane == 0) out[j] = accv + b2[j];
}

extern "C" void kernel_launch(void* const* d_in, const int* in_sizes, int n_in,
                              void* d_out, int out_size) {
    const int*   words       = (const int*)d_in[0];
    const int*   wic         = (const int*)d_in[1];
    const float* word_emb    = (const float*)d_in[2];
    const float* chr_emb     = (const float*)d_in[3];
    const float* conv_chr_w  = (const float*)d_in[4];
    const float* conv_chr_b  = (const float*)d_in[5];
    const float* conv_sent_w = (const float*)d_in[6];
    const float* conv_sent_b = (const float*)d_in[7];
    const float* w1          = (const float*)d_in[8];
    const float* b1          = (const float*)d_in[9];
    const float* w2          = (const float*)d_in[10];
    const float* b2          = (const float*)d_in[11];
    float* out = (float*)d_out;

    cudaFuncSetAttribute(k_gemm_mma, cudaFuncAttributeMaxDynamicSharedMemorySize, SMEM_DYN);

    k_tr_wc<<<768, 256>>>(conv_chr_w);
    k_prep_B<<<512, 256>>>(conv_sent_w);
    k_tables<<<64, 256>>>(chr_emb);
    k_build_u<<<W_WORDS, 128>>>(words, wic, word_emb, conv_chr_b);
    dim3 g3(D2 / GN, W_WORDS / GM);     // 8 x 32 = 256 CTAs
    k_gemm_mma<<<g3, 256, SMEM_DYN>>>();
    k_h<<<64, 256>>>(conv_sent_b, w1, b1);
    k_out<<<1, 64>>>(w2, b2, out);
}

// round 8
// speedup vs baseline: 1.9734x; 1.3387x over previous
#include <cuda_runtime.h>
#include <cuda_bf16.h>
#include <cuda_fp16.h>
#include <cstdint>

// Sizes
#define W_WORDS 4096
#define LCH 32
#define D2 512
#define D4 1024
#define KDIM 1536   // 3*512

// GEMM tiling
#define GM 128
#define GN 64
#define GK 32
#define NK (KDIM / GK)            // 48
#define A_TILE (GM * GK * 2)      // 8192 B (fp16)
#define B_TILE (GN * GK * 2)      // 4096 B
#define STAGE_B (A_TILE + B_TILE) // 12288
#define NSTAGE 3
#define SMEM_DYN (NSTAGE * STAGE_B)         // 36864

// ---------------- scratch ----------------
__device__ __align__(128) __half g_Wth[3 * 256 * 256];       // char conv w transposed, fp16
__device__ __align__(128) __half g_Th[3 * 128 * 256];        // fp16 lookup tables
__device__ __align__(128) __half g_ua[(W_WORDS + 2) * D2];   // u in fp16
__device__ __align__(128) __half g_Bh[D2 * KDIM];            // B fp16 [o][p] K-major
__device__ __align__(128) unsigned g_rkeys[D2];
__device__ __align__(128) float  g_h[D4];

// ---------------- helpers ----------------
__device__ __forceinline__ uint32_t smem_u32(const void* p) {
    uint32_t a;
    asm("{ .reg .u64 t; cvta.to.shared.u64 t, %1; cvt.u32.u64 %0, t; }" : "=r"(a) : "l"(p));
    return a;
}
__device__ __forceinline__ void ldmx4(uint32_t* r, uint32_t addr) {
    asm volatile("ldmatrix.sync.aligned.m8n8.x4.shared.b16 {%0,%1,%2,%3}, [%4];"
                 : "=r"(r[0]), "=r"(r[1]), "=r"(r[2]), "=r"(r[3]) : "r"(addr));
}
__device__ __forceinline__ void mma_f16(float* c, const uint32_t* a, uint32_t b0, uint32_t b1) {
    asm volatile("mma.sync.aligned.m16n8k16.row.col.f32.f16.f16.f32 "
                 "{%0,%1,%2,%3}, {%4,%5,%6,%7}, {%8,%9}, {%0,%1,%2,%3};"
                 : "+f"(c[0]), "+f"(c[1]), "+f"(c[2]), "+f"(c[3])
                 : "r"(a[0]), "r"(a[1]), "r"(a[2]), "r"(a[3]), "r"(b0), "r"(b1));
}
__device__ __forceinline__ void cp16(uint32_t dst, const void* src) {
    asm volatile("cp.async.cg.shared.global [%0], [%1], 16;" :: "r"(dst), "l"(src));
}
#define CP_COMMIT() asm volatile("cp.async.commit_group;" ::: "memory")
#define CP_WAIT1()  asm volatile("cp.async.wait_group 1;" ::: "memory")

// ---------------- prep: transpose char-w (fp16) + convert sentence-w (merged) ----------------
__global__ void k_prep(const float* __restrict__ wc, const float* __restrict__ ws) {
    int b = blockIdx.x;
    if (b < 768) {                 // wc: [d][i][k] -> g_Wth[k][i][d]
        int k = b / 256, i = b % 256;
        int d = threadIdx.x;
        g_Wth[k * 65536 + i * 256 + d] = __float2half(wc[d * 768 + i * 3 + k]);
    } else {                       // ws -> Bh, K-major [o][p]
        int o = b - 768;           // 512
        for (int p = threadIdx.x; p < KDIM; p += 256) {
            int kk = p >> 9, i = p & 511;
            g_Bh[o * KDIM + p] = __float2half(ws[o * KDIM + i * 3 + kk]);
        }
        if (o == 0) { g_rkeys[threadIdx.x] = 0u; g_rkeys[threadIdx.x + 256] = 0u; }
    }
}

// ---------------- char tables: fp16 weights, fp32 accum, fp16 store ----------------
__global__ void k_tables(const float* __restrict__ chr_emb) {
    __shared__ float ce[2][256];
    int d = threadIdx.x;
    int c0 = blockIdx.x * 2;
    ce[0][d] = chr_emb[c0 * 256 + d];
    ce[1][d] = chr_emb[(c0 + 1) * 256 + d];
    __syncthreads();
    float a00 = 0.f, a01 = 0.f, a02 = 0.f, a10 = 0.f, a11 = 0.f, a12 = 0.f;
    #pragma unroll 8
    for (int i = 0; i < 256; i++) {
        float e0 = ce[0][i], e1 = ce[1][i];
        float w0 = __half2float(g_Wth[i * 256 + d]);
        float w1 = __half2float(g_Wth[65536 + i * 256 + d]);
        float w2 = __half2float(g_Wth[131072 + i * 256 + d]);
        a00 += e0 * w0; a01 += e0 * w1; a02 += e0 * w2;
        a10 += e1 * w0; a11 += e1 * w1; a12 += e1 * w2;
    }
    g_Th[c0 * 256 + d]                  = __float2half(a00);
    g_Th[32768 + c0 * 256 + d]          = __float2half(a01);
    g_Th[65536 + c0 * 256 + d]          = __float2half(a02);
    g_Th[(c0 + 1) * 256 + d]            = __float2half(a10);
    g_Th[32768 + (c0 + 1) * 256 + d]    = __float2half(a11);
    g_Th[65536 + (c0 + 1) * 256 + d]    = __float2half(a12);
}

// ---------------- build u: half2 arithmetic throughout ----------------
__global__ void k_build_u(const int* __restrict__ words,
                          const int* __restrict__ wic,
                          const float* __restrict__ word_emb,
                          const float* __restrict__ cb) {
    int w = blockIdx.x;            // 4096
    int t = threadIdx.x;           // 128
    __shared__ int codes[LCH];
    if (t < LCH) codes[t] = wic[w * LCH + t];
    __syncthreads();

    const float2* WE = (const float2*)word_emb;
    float2 wv = WE[(size_t)words[w] * 128 + t];
    __half2* UA = (__half2*)g_ua;  // row = 256 half2
    UA[(w + 1) * 256 + t] = __floats2half2_rn(wv.x, wv.y);

    const __half2* T0 = (const __half2*)g_Th;            // each table = 16384 half2
    const __half2* T1 = T0 + 16384;
    const __half2* T2 = T0 + 32768;
    float2 cbv = ((const float2*)cb)[t];
    __half2 bb = __floats2half2_rn(cbv.x, cbv.y);

    int c = codes[0];
    __half2 a0 = T0[c * 128 + t];
    __half2 a1 = T1[c * 128 + t];
    __half2 a2 = T2[c * 128 + t];
    __half2 accA = __hadd2(bb, a1);
    __half2 accB = __hadd2(bb, a0);
    __half2 m = __half2half2(__float2half(-60000.0f));
    (void)a2;
    #pragma unroll
    for (int s = 1; s < LCH; s++) {
        c = codes[s];
        a0 = T0[c * 128 + t];
        a1 = T1[c * 128 + t];
        a2 = T2[c * 128 + t];
        m = __hmax2(m, __hadd2(accA, a2));
        accA = __hadd2(accB, a1);
        accB = __hadd2(bb, a0);
    }
    m = __hmax2(m, accA);
    UA[(w + 1) * 256 + 128 + t] = m;

    __half2 z = __floats2half2_rn(0.f, 0.f);
    if (w == 0) { UA[t] = z; UA[128 + t] = z; }
    if (w == W_WORDS - 1) {
        size_t r = (size_t)(W_WORDS + 1) * 256;
        UA[r + t] = z; UA[r + 128 + t] = z;
    }
}

// ---------------- GEMM: single-product fp16 + fused column max ----------------
__global__ __launch_bounds__(256, 2) void k_gemm_mma() {
    extern __shared__ __align__(128) char smem[];
    uint32_t sb = smem_u32(smem);
    int tid = threadIdx.x;
    int lane = tid & 31, wq = tid >> 5;
    int wm = wq & 3, wn = wq >> 2;       // 4 m-warps x 2 n-warps; warp tile 32x32
    int n0 = blockIdx.x * GN;
    int w0 = blockIdx.y * GM;

    float acc[2][4][4];
    #pragma unroll
    for (int a = 0; a < 2; a++)
        #pragma unroll
        for (int f = 0; f < 4; f++)
            #pragma unroll
            for (int r = 0; r < 4; r++) acc[a][f][r] = 0.f;

    auto issue_stage = [&](int ck, int s) {
        int p0 = ck * GK;
        int kk = p0 >> 9, i0 = p0 & 511;
        uint32_t st = sb + s * STAGE_B;
        #pragma unroll
        for (int q = 0; q < 3; q++) {
            int idx = tid + q * 256;      // 0..767
            if (idx < 512) {              // A tile: 512 x 16B
                int r = idx >> 2, c4 = idx & 3;
                uint32_t dst = st + r * 64 + ((c4 ^ ((r >> 1) & 3)) << 4);
                const __half* src = g_ua + (size_t)(w0 + kk + r) * D2 + i0 + c4 * 8;
                cp16(dst, src);
            } else {                      // B tile: 256 x 16B
                int j = idx - 512;
                int r = j >> 2, c4 = j & 3;
                uint32_t dst = st + A_TILE + r * 64 + ((c4 ^ ((r >> 1) & 3)) << 4);
                const __half* src = g_Bh + (size_t)(n0 + r) * KDIM + p0 + c4 * 8;
                cp16(dst, src);
            }
        }
        CP_COMMIT();
    };

    issue_stage(0, 0);
    issue_stage(1, 1);

    for (int ck = 0; ck < NK; ck++) {
        CP_WAIT1();
        __syncthreads();
        if (ck + 2 < NK) issue_stage(ck + 2, (ck + 2) % NSTAGE);
        else CP_COMMIT();

        uint32_t st = sb + (ck % NSTAGE) * STAGE_B;
        uint32_t aA = st, bH = st + A_TILE;
        #pragma unroll
        for (int ks = 0; ks < 2; ks++) {
            uint32_t ah[2][4];
            #pragma unroll
            for (int mf = 0; mf < 2; mf++) {
                int row = wm * 32 + mf * 16 + (lane & 7) + ((lane >> 3) & 1) * 8;
                int c = 2 * ks + (lane >> 4);
                uint32_t off = (uint32_t)(row * 64) + (uint32_t)((c ^ ((row >> 1) & 3)) << 4);
                ldmx4(ah[mf], aA + off);
            }
            #pragma unroll
            for (int bq = 0; bq < 2; bq++) {
                int row = wn * 32 + bq * 16 + (lane & 7) + ((lane >> 3) & 1) * 8;
                int c = 2 * ks + (lane >> 4);
                uint32_t off = (uint32_t)(row * 64) + (uint32_t)((c ^ ((row >> 1) & 3)) << 4);
                uint32_t bh[4];
                ldmx4(bh, bH + off);
                #pragma unroll
                for (int mf = 0; mf < 2; mf++) {
                    mma_f16(acc[mf][2 * bq],     ah[mf], bh[0], bh[2]);
                    mma_f16(acc[mf][2 * bq + 1], ah[mf], bh[1], bh[3]);
                }
            }
        }
    }

    // epilogue: column max over tile's 128 rows
    __syncthreads();
    float* red = (float*)smem;   // [4 wm][64 cols]
    #pragma unroll
    for (int f = 0; f < 4; f++) {
        float t0 = -1e30f, t1 = -1e30f;
        #pragma unroll
        for (int mf = 0; mf < 2; mf++) {
            t0 = fmaxf(t0, fmaxf(acc[mf][f][0], acc[mf][f][2]));
            t1 = fmaxf(t1, fmaxf(acc[mf][f][1], acc[mf][f][3]));
        }
        #pragma unroll
        for (int off = 4; off < 32; off <<= 1) {
            t0 = fmaxf(t0, __shfl_xor_sync(0xffffffffu, t0, off));
            t1 = fmaxf(t1, __shfl_xor_sync(0xffffffffu, t1, off));
        }
        if (lane < 4) {
            red[wm * 64 + wn * 32 + f * 8 + 2 * lane]     = t0;
            red[wm * 64 + wn * 32 + f * 8 + 2 * lane + 1] = t1;
        }
    }
    __syncthreads();
    if (tid < 64) {
        float m = red[tid];
        #pragma unroll
        for (int q = 1; q < 4; q++) m = fmaxf(m, red[q * 64 + tid]);
        unsigned u = __float_as_uint(m);
        unsigned key = (u & 0x80000000u) ? ~u : (u | 0x80000000u);
        atomicMax(&g_rkeys[n0 + tid], key);
    }
}

// ---------------- head ----------------
__global__ void k_h(const float* __restrict__ sb,
                    const float* __restrict__ w1,
                    const float* __restrict__ b1) {
    __shared__ float rs[D2];
    int tid = threadIdx.x;
    for (int j = tid; j < D2; j += 256) {
        unsigned key = g_rkeys[j];
        unsigned u = (key & 0x80000000u) ? (key & 0x7FFFFFFFu) : ~key;
        rs[j] = __uint_as_float(u) + sb[j];
    }
    __syncthreads();
    int g = tid >> 4, s = tid & 15;
    int o = blockIdx.x * 16 + g;
    float accv = 0.f;
    for (int j = s; j < D2; j += 16) accv += w1[o * D2 + j] * rs[j];
    #pragma unroll
    for (int off = 8; off; off >>= 1) accv += __shfl_down_sync(0xffffffffu, accv, off, 16);
    if (s == 0) g_h[o] = tanhf(accv + b1[o]);
}

__global__ void k_out(const float* __restrict__ w2,
                      const float* __restrict__ b2,
                      float* __restrict__ out) {
    int j = threadIdx.x >> 5, lane = threadIdx.x & 31;
    float accv = 0.f;
    for (int l = lane; l < D4; l += 32) accv += g_h[l] * w2[j * D4 + l];
    #pragma unroll
    for (int off = 16; off; off >>= 1) accv += __shfl_down_sync(0xffffffffu, accv, off);
    if (lane == 0) out[j] = accv + b2[j];
}

extern "C" void kernel_launch(void* const* d_in, const int* in_sizes, int n_in,
                              void* d_out, int out_size) {
    const int*   words       = (const int*)d_in[0];
    const int*   wic         = (const int*)d_in[1];
    const float* word_emb    = (const float*)d_in[2];
    const float* chr_emb     = (const float*)d_in[3];
    const float* conv_chr_w  = (const float*)d_in[4];
    const float* conv_chr_b  = (const float*)d_in[5];
    const float* conv_sent_w = (const float*)d_in[6];
    const float* conv_sent_b = (const float*)d_in[7];
    const float* w1          = (const float*)d_in[8];
    const float* b1          = (const float*)d_in[9];
    const float* w2          = (const float*)d_in[10];
    const float* b2          = (const float*)d_in[11];
    float* out = (float*)d_out;

    cudaFuncSetAttribute(k_gemm_mma, cudaFuncAttributeMaxDynamicSharedMemorySize, SMEM_DYN);

    k_prep<<<1280, 256>>>(conv_chr_w, conv_sent_w);
    k_tables<<<64, 256>>>(chr_emb);
    k_build_u<<<W_WORDS, 128>>>(words, wic, word_emb, conv_chr_b);
    dim3 g3(D2 / GN, W_WORDS / GM);     // 8 x 32 = 256 CTAs
    k_gemm_mma<<<g3, 256, SMEM_DYN>>>();
    k_h<<<64, 256>>>(conv_sent_b, w1, b1);
    k_out<<<1, 64>>>(w2, b2, out);
}